// round 3
// baseline (speedup 1.0000x reference)
#include <cuda_runtime.h>

#define BB 8
#define CC 32
#define HH 384
#define WW 768
#define HW  (HH * WW)               // 294912
#define CHW (CC * HH * WW)          // 9437184  (fits int32)
#define NPIX (BB * HH * WW)         // 2359296

__global__ __launch_bounds__(256, 8)
void disparity_warp_k3(const float* __restrict__ src,
                       const float* __restrict__ disp,
                       float* __restrict__ out) {
    const int idx = blockIdx.x * 256 + threadIdx.x;   // grid exact, no guard

    const int w = idx % WW;
    const int t = idx / WW;
    const int h = t % HH;
    const int b = t / HH;

    const float d  = disp[idx];
    const float ix = ((float)w - d) * (768.0f / 767.0f) - 0.5f;
    const float iy = (float)h * (384.0f / 383.0f) - 0.5f;

    const float x0f = floorf(ix);
    const float y0f = floorf(iy);
    const float fx = ix - x0f;
    const float fy = iy - y0f;
    const int x0 = (int)x0f, x1 = x0 + 1;
    const int y0 = (int)y0f, y1 = y0 + 1;

    // zero-padding: fold OOB mask into weights, clamp indices for the load
    const bool xi0 = (x0 >= 0) & (x0 < WW);
    const bool xi1 = (x1 >= 0) & (x1 < WW);
    const bool yi0 = (y0 >= 0) & (y0 < HH);
    const bool yi1 = (y1 >= 0) & (y1 < HH);

    const float w00 = (1.0f - fy) * (1.0f - fx) * (float)(xi0 & yi0);
    const float w01 = (1.0f - fy) * fx          * (float)(xi1 & yi0);
    const float w10 = fy * (1.0f - fx)          * (float)(xi0 & yi1);
    const float w11 = fy * fx                   * (float)(xi1 & yi1);

    const int cx0 = min(max(x0, 0), WW - 1);
    const int cx1 = min(max(x1, 0), WW - 1);
    const int cy0 = min(max(y0, 0), HH - 1);
    const int cy1 = min(max(y1, 0), HH - 1);

    // loop-invariant gather offsets (int32)
    const int o00 = cy0 * WW + cx0;
    const int o01 = cy0 * WW + cx1;
    const int o10 = cy1 * WW + cx0;
    const int o11 = cy1 * WW + cx1;

    const float* p = src + b * CHW;                 // advance by HW per channel
    float* o = out + b * CHW + h * WW + w;

    #pragma unroll 4
    for (int c = 0; c < CC; ++c) {
        const float v = p[o00] * w00 + p[o01] * w01
                      + p[o10] * w10 + p[o11] * w11;
        *o = v;
        p += HW;
        o += HW;
    }
}

extern "C" void kernel_launch(void* const* d_in, const int* in_sizes, int n_in,
                              void* d_out, int out_size) {
    const float* src  = (const float*)d_in[0];
    const float* disp = (const float*)d_in[1];
    float* out = (float*)d_out;

    disparity_warp_k3<<<NPIX / 256, 256>>>(src, disp, out);
}

// round 4
// speedup vs baseline: 1.0874x; 1.0874x over previous
#include <cuda_runtime.h>

#define BB 8
#define CC 32
#define HH 384
#define WW 768
#define HW  (HH * WW)               // 294912
#define CHW (CC * HH * WW)          // 9437184 (fits int32)
#define NPIX (BB * HH * WW)         // 2359296

__global__ __launch_bounds__(256)
void disparity_warp_k4(const float* __restrict__ src,
                       const float* __restrict__ disp,
                       float* __restrict__ out) {
    const int idx = blockIdx.x * 256 + threadIdx.x;   // grid exact, no guard

    const int w = idx % WW;
    const int t = idx / WW;
    const int h = t % HH;
    const int b = t / HH;

    const float d  = disp[idx];
    const float ix = ((float)w - d) * (768.0f / 767.0f) - 0.5f;
    const float iy = (float)h * (384.0f / 383.0f) - 0.5f;

    const float x0f = floorf(ix);
    const float y0f = floorf(iy);
    const float fx = ix - x0f;
    const float fy = iy - y0f;
    const int x0 = (int)x0f, x1 = x0 + 1;
    const int y0 = (int)y0f, y1 = y0 + 1;

    // zero-padding: fold OOB mask into weights, clamp indices for the load
    const bool xi0 = (x0 >= 0) & (x0 < WW);
    const bool xi1 = (x1 >= 0) & (x1 < WW);
    const bool yi0 = (y0 >= 0) & (y0 < HH);
    const bool yi1 = (y1 >= 0) & (y1 < HH);

    const float w00 = (1.0f - fy) * (1.0f - fx) * (float)(xi0 & yi0);
    const float w01 = (1.0f - fy) * fx          * (float)(xi1 & yi0);
    const float w10 = fy * (1.0f - fx)          * (float)(xi0 & yi1);
    const float w11 = fy * fx                   * (float)(xi1 & yi1);

    const int cx0 = min(max(x0, 0), WW - 1);
    const int cx1 = min(max(x1, 0), WW - 1);
    const int cy0 = min(max(y0, 0), HH - 1);
    const int cy1 = min(max(y1, 0), HH - 1);

    // loop-invariant gather offsets (int32)
    const int o00 = cy0 * WW + cx0;
    const int o01 = cy0 * WW + cx1;
    const int o10 = cy1 * WW + cx0;
    const int o11 = cy1 * WW + cx1;

    const float* p = src + b * CHW;
    float* o = out + b * CHW + h * WW + w;

    #pragma unroll 8
    for (int c = 0; c < CC; ++c) {
        const float a0 = p[o00];
        const float a1 = p[o01];
        const float a2 = p[o10];
        const float a3 = p[o11];
        // two independent FMA pairs -> shorter dependency chain
        const float t0 = fmaf(a1, w01, a0 * w00);
        const float t1 = fmaf(a3, w11, a2 * w10);
        *o = t0 + t1;
        p += HW;
        o += HW;
    }
}

extern "C" void kernel_launch(void* const* d_in, const int* in_sizes, int n_in,
                              void* d_out, int out_size) {
    const float* src  = (const float*)d_in[0];
    const float* disp = (const float*)d_in[1];
    float* out = (float*)d_out;

    disparity_warp_k4<<<NPIX / 256, 256>>>(src, disp, out);
}

// round 5
// speedup vs baseline: 1.1952x; 1.0991x over previous
#include <cuda_runtime.h>

#define BB 8
#define CC 32
#define HH 384
#define WW 768
#define NPIX (BB * HH * WW)          // 2359296
#define CHW  ((size_t)CC * HH * WW)
#define HW   ((size_t)HH * WW)

__global__ __launch_bounds__(256)
void disparity_warp_k5(const float* __restrict__ src,
                       const float* __restrict__ disp,
                       float* __restrict__ out) {
    int idx = blockIdx.x * 256 + threadIdx.x;

    int w = idx % WW;
    int t = idx / WW;
    int h = t % HH;
    int b = t / HH;

    float d = disp[idx];
    float ix = ((float)w - d) * (768.0f / 767.0f) - 0.5f;
    float iy = (float)h * (384.0f / 383.0f) - 0.5f;

    float x0f = floorf(ix);
    float y0f = floorf(iy);
    float fx = ix - x0f;
    float fy = iy - y0f;
    int x0 = (int)x0f, y0 = (int)y0f;
    int x1 = x0 + 1,  y1 = y0 + 1;

    // zero-padding: fold OOB mask into weights, clamp indices for the load
    bool xi0 = (x0 >= 0) & (x0 < WW);
    bool xi1 = (x1 >= 0) & (x1 < WW);
    bool yi0 = (y0 >= 0) & (y0 < HH);
    bool yi1 = (y1 >= 0) & (y1 < HH);

    float w00 = (1.0f - fy) * (1.0f - fx) * (float)(xi0 & yi0);
    float w01 = (1.0f - fy) * fx          * (float)(xi1 & yi0);
    float w10 = fy * (1.0f - fx)          * (float)(xi0 & yi1);
    float w11 = fy * fx                   * (float)(xi1 & yi1);

    int cx0 = min(max(x0, 0), WW - 1);
    int cx1 = min(max(x1, 0), WW - 1);
    int cy0 = min(max(y0, 0), HH - 1);
    int cy1 = min(max(y1, 0), HH - 1);

    int o00 = cy0 * WW + cx0;
    int o01 = cy0 * WW + cx1;
    int o10 = cy1 * WW + cx0;
    int o11 = cy1 * WW + cx1;

    const float* sb = src + (size_t)b * CHW;
    float* ob = out + (size_t)b * CHW + (size_t)h * WW + w;

    #pragma unroll 16
    for (int c = 0; c < CC; ++c) {
        const float* p = sb + (size_t)c * HW;
        float v = p[o00] * w00 + p[o01] * w01 + p[o10] * w10 + p[o11] * w11;
        ob[(size_t)c * HW] = v;
    }
}

extern "C" void kernel_launch(void* const* d_in, const int* in_sizes, int n_in,
                              void* d_out, int out_size) {
    const float* src  = (const float*)d_in[0];
    const float* disp = (const float*)d_in[1];
    float* out = (float*)d_out;

    disparity_warp_k5<<<NPIX / 256, 256>>>(src, disp, out);
}